// round 10
// baseline (speedup 1.0000x reference)
#include <cuda_runtime.h>
#include <cstdint>

// ---------------------------------------------------------------------------
// BatchedSequences: scatter concatenated rows S[T,F] into padded out[B,MAX,F],
// zero-filling padding. HBM-roofline copy (plateau ~6.2-6.3 TB/s mixed R/W).
// R10: R9 (best: .cs + L2::256B read hint) with 256-bit reads stacked on the
//      hint in the full-valid path: ld.global.cs.L2::256B.v8.f32.
// ---------------------------------------------------------------------------

#define MAX_B 4096
__device__ int       g_len[MAX_B];
__device__ long long g_off[MAX_B];

// streaming 128-bit load with 256B L2 prefetch granule
__device__ __forceinline__ float4 ldcs256(const float4* p) {
    float4 v;
    asm volatile("ld.global.cs.L2::256B.v4.f32 {%0,%1,%2,%3}, [%4];"
                 : "=f"(v.x), "=f"(v.y), "=f"(v.z), "=f"(v.w)
                 : "l"(p));
    return v;
}
// streaming 256-bit load with 256B L2 prefetch granule (sm_100+)
__device__ __forceinline__ void ldcs256_v8(const float4* p, float4& a, float4& b) {
    asm volatile("ld.global.cs.L2::256B.v8.f32 {%0,%1,%2,%3,%4,%5,%6,%7}, [%8];"
                 : "=f"(a.x), "=f"(a.y), "=f"(a.z), "=f"(a.w),
                   "=f"(b.x), "=f"(b.y), "=f"(b.z), "=f"(b.w)
                 : "l"(p));
}

// ---- generic fallback path (any B / shapes) --------------------------------
__global__ void build_offsets_kernel(const void* __restrict__ lens_raw,
                                     int B, long long T) {
    if (threadIdx.x == 0) {
        const int* v32 = (const int*)lens_raw;
        long long s = 0;
        for (int i = 0; i < B; ++i) s += (long long)v32[i];
        const bool is32 = (s == T);
        const long long* v64 = (const long long*)lens_raw;
        long long off = 0;
        for (int i = 0; i < B; ++i) {
            long long L = is32 ? (long long)v32[i] : v64[i];
            g_len[i] = (int)L;
            g_off[i] = off;
            off += L;
        }
    }
}

__global__ void __launch_bounds__(256)
pad_scatter_generic(const float4* __restrict__ in4,
                    float4* __restrict__ out4,
                    int total, int F4, int max_sl) {
    int idx = blockIdx.x * blockDim.x + threadIdx.x;
    if (idx >= total) return;
    int c   = idx % F4;
    int row = idx / F4;
    int b   = row / max_sl;
    int p   = row - b * max_sl;
    float4 v = make_float4(0.f, 0.f, 0.f, 0.f);
    if (p < g_len[b])
        v = __ldcs(&in4[(g_off[b] + (long long)p) * F4 + c]);
    __stcs(&out4[idx], v);
}

// ---- fused fast path (B <= 32, F4/MAX powers of two) ------------------------
// One block per CHUNK=1024 contiguous float4 (= 8 rows of F4=128). CHUNK
// divides MAX*F4, so the batch index is block-uniform and the len boundary
// cuts at most one chunk per batch. Source within a chunk is contiguous:
// src[e] = in4[(off+p0)*F4 + e]. Full-valid chunks use 256-bit reads with
// 256B L2 granules (2 pair-units per thread).
template <int F4_LOG2, int MAX_LOG2, int VPT>
__global__ void __launch_bounds__(256)
fused_pad_scatter(const float4* __restrict__ in4,
                  float4* __restrict__ out4,
                  const void* __restrict__ lens_raw,
                  int B) {
    constexpr unsigned FULL  = 0xFFFFFFFFu;
    constexpr int CHUNK = 256 * VPT;
    constexpr int ROWS  = CHUNK >> F4_LOG2;          // rows per chunk
    constexpr int VPT32 = VPT / 2;                   // 32B pair-units / thread

    const int tid  = threadIdx.x;
    const int lane = tid & 31;
    const int base = (int)blockIdx.x * CHUNK;
    const int b    = base >> (F4_LOG2 + MAX_LOG2);   // block-uniform

    // dtype probe: read first B int32 words (in-bounds for both layouts).
    // int32 lengths are positive -> some odd word nonzero; int64 (LE,
    // values < 2^31) -> odd words are all-zero high halves.
    const int* v32 = (const int*)lens_raw;
    int w = (lane < B) ? __ldg(&v32[lane]) : 0;
    const bool is32 = __ballot_sync(FULL, (lane & 1) && (w != 0)) != 0;
    int val = w;
    if (!is32) {                                     // warp-uniform branch
        const long long* v64 = (const long long*)lens_raw;
        val = (lane < B) ? (int)__ldg(&v64[lane]) : 0;
    }
    int incl = val;                                  // inclusive warp scan
    #pragma unroll
    for (int d = 1; d < 32; d <<= 1) {
        int y = __shfl_up_sync(FULL, incl, d);
        if (lane >= d) incl += y;
    }
    const int len = __shfl_sync(FULL, val,        b);
    const int off = __shfl_sync(FULL, incl - val, b);

    const int p0 = (base >> F4_LOG2) & ((1 << MAX_LOG2) - 1);  // first row
    float4* __restrict__ outp = out4 + base;

    if (p0 >= len) {
        // all-padding chunk: streaming zero stores only
        const float4 z = make_float4(0.f, 0.f, 0.f, 0.f);
        #pragma unroll
        for (int k = 0; k < VPT; ++k)
            __stcs(&outp[tid + k * 256], z);
    } else {
        const float4* __restrict__ src = in4 + ((off + p0) << F4_LOG2);
        if (p0 + ROWS <= len) {
            // fully valid chunk: 256-bit reads + 256B L2 granules
            float4 a[VPT32], c[VPT32];
            #pragma unroll
            for (int k = 0; k < VPT32; ++k)
                ldcs256_v8(&src[(tid + k * 256) * 2], a[k], c[k]);
            #pragma unroll
            for (int k = 0; k < VPT32; ++k) {
                __stcs(&outp[(tid + k * 256) * 2],     a[k]);
                __stcs(&outp[(tid + k * 256) * 2 + 1], c[k]);
            }
        } else {
            // boundary chunk (<= 1 per batch): predicated, 128-bit
            const int valid_e = (len - p0) << F4_LOG2;
            #pragma unroll
            for (int k = 0; k < VPT; ++k) {
                const int e = tid + k * 256;
                float4 v = make_float4(0.f, 0.f, 0.f, 0.f);
                if (e < valid_e) v = ldcs256(&src[e]);
                __stcs(&outp[e], v);
            }
        }
    }
}

extern "C" void kernel_launch(void* const* d_in, const int* in_sizes, int n_in,
                              void* d_out, int out_size) {
    const int F  = 512;
    const int F4 = F / 4;                                    // 128
    const int B  = in_sizes[1];
    const long long T = (long long)in_sizes[0] / F;
    const int max_sl = (int)((long long)out_size / ((long long)B * F));
    const int total  = out_size / 4;                         // float4 count

    if (F4 == 128 && max_sl == 4096 && B <= 32 && (total % 1024) == 0 &&
        T <= 0x7FFFFFFFLL) {
        fused_pad_scatter<7, 12, 4><<<total / 1024, 256>>>(
            (const float4*)d_in[0], (float4*)d_out, d_in[1], B);
    } else {
        build_offsets_kernel<<<1, 32>>>(d_in[1], B, T);
        pad_scatter_generic<<<(total + 255) / 256, 256>>>(
            (const float4*)d_in[0], (float4*)d_out, total, F4, max_sl);
    }
}

// round 11
// speedup vs baseline: 1.0278x; 1.0278x over previous
#include <cuda_runtime.h>
#include <cstdint>

// ---------------------------------------------------------------------------
// BatchedSequences: scatter concatenated rows S[T,F] into padded out[B,MAX,F],
// zero-filling padding. HBM-roofline copy.
// FINAL (= R9, best measured: 66.2us kernel, 6269 GB/s, 79.1% DRAM):
//   - single fused kernel, no prologue: per-block warp scan of lengths with
//     int32/int64 auto-detection (ballot probe on odd words)
//   - one block per 1024 contiguous float4 (8 rows); batch index is
//     block-uniform, so chunks specialize 3 ways: full-copy / all-padding /
//     boundary (<=1 per batch)
//   - 128-bit .cs streaming accesses; loads carry an L2::256B prefetch-
//     granule hint (sequential reads -> longer DRAM bursts). Measured A/Bs:
//     v8.f32 neutral alone, regressive stacked with the hint; write-back
//     stores regressive; persistent grid regressive.
// ---------------------------------------------------------------------------

#define MAX_B 4096
__device__ int       g_len[MAX_B];
__device__ long long g_off[MAX_B];

// streaming load with 256B L2 prefetch granule
__device__ __forceinline__ float4 ldcs256(const float4* p) {
    float4 v;
    asm volatile("ld.global.cs.L2::256B.v4.f32 {%0,%1,%2,%3}, [%4];"
                 : "=f"(v.x), "=f"(v.y), "=f"(v.z), "=f"(v.w)
                 : "l"(p));
    return v;
}

// ---- generic fallback path (any B / shapes) --------------------------------
__global__ void build_offsets_kernel(const void* __restrict__ lens_raw,
                                     int B, long long T) {
    if (threadIdx.x == 0) {
        const int* v32 = (const int*)lens_raw;
        long long s = 0;
        for (int i = 0; i < B; ++i) s += (long long)v32[i];
        const bool is32 = (s == T);
        const long long* v64 = (const long long*)lens_raw;
        long long off = 0;
        for (int i = 0; i < B; ++i) {
            long long L = is32 ? (long long)v32[i] : v64[i];
            g_len[i] = (int)L;
            g_off[i] = off;
            off += L;
        }
    }
}

__global__ void __launch_bounds__(256)
pad_scatter_generic(const float4* __restrict__ in4,
                    float4* __restrict__ out4,
                    int total, int F4, int max_sl) {
    int idx = blockIdx.x * blockDim.x + threadIdx.x;
    if (idx >= total) return;
    int c   = idx % F4;
    int row = idx / F4;
    int b   = row / max_sl;
    int p   = row - b * max_sl;
    float4 v = make_float4(0.f, 0.f, 0.f, 0.f);
    if (p < g_len[b])
        v = __ldcs(&in4[(g_off[b] + (long long)p) * F4 + c]);
    __stcs(&out4[idx], v);
}

// ---- fused fast path (B <= 32, F4/MAX powers of two) ------------------------
// One block per CHUNK=1024 contiguous float4 (= 8 rows of F4=128). CHUNK
// divides MAX*F4, so the batch index is block-uniform and the len boundary
// cuts at most one chunk per batch. Source within a chunk is contiguous:
// src[e] = in4[(off+p0)*F4 + e].
template <int F4_LOG2, int MAX_LOG2, int VPT>
__global__ void __launch_bounds__(256)
fused_pad_scatter(const float4* __restrict__ in4,
                  float4* __restrict__ out4,
                  const void* __restrict__ lens_raw,
                  int B) {
    constexpr unsigned FULL  = 0xFFFFFFFFu;
    constexpr int CHUNK = 256 * VPT;
    constexpr int ROWS  = CHUNK >> F4_LOG2;          // rows per chunk

    const int tid  = threadIdx.x;
    const int lane = tid & 31;
    const int base = (int)blockIdx.x * CHUNK;
    const int b    = base >> (F4_LOG2 + MAX_LOG2);   // block-uniform

    // dtype probe: read first B int32 words (in-bounds for both layouts).
    // int32 lengths are positive -> some odd word nonzero; int64 (LE,
    // values < 2^31) -> odd words are all-zero high halves.
    const int* v32 = (const int*)lens_raw;
    int w = (lane < B) ? __ldg(&v32[lane]) : 0;
    const bool is32 = __ballot_sync(FULL, (lane & 1) && (w != 0)) != 0;
    int val = w;
    if (!is32) {                                     // warp-uniform branch
        const long long* v64 = (const long long*)lens_raw;
        val = (lane < B) ? (int)__ldg(&v64[lane]) : 0;
    }
    int incl = val;                                  // inclusive warp scan
    #pragma unroll
    for (int d = 1; d < 32; d <<= 1) {
        int y = __shfl_up_sync(FULL, incl, d);
        if (lane >= d) incl += y;
    }
    const int len = __shfl_sync(FULL, val,        b);
    const int off = __shfl_sync(FULL, incl - val, b);

    const int p0 = (base >> F4_LOG2) & ((1 << MAX_LOG2) - 1);  // first row
    float4* __restrict__ outp = out4 + base;

    if (p0 >= len) {
        // all-padding chunk: streaming zero stores only
        const float4 z = make_float4(0.f, 0.f, 0.f, 0.f);
        #pragma unroll
        for (int k = 0; k < VPT; ++k)
            __stcs(&outp[tid + k * 256], z);
    } else {
        const float4* __restrict__ src = in4 + ((off + p0) << F4_LOG2);
        if (p0 + ROWS <= len) {
            // fully valid chunk: streaming copy with 256B L2 read granules
            float4 v[VPT];
            #pragma unroll
            for (int k = 0; k < VPT; ++k)
                v[k] = ldcs256(&src[tid + k * 256]);
            #pragma unroll
            for (int k = 0; k < VPT; ++k)
                __stcs(&outp[tid + k * 256], v[k]);
        } else {
            // boundary chunk (<= 1 per batch): predicated
            const int valid_e = (len - p0) << F4_LOG2;
            #pragma unroll
            for (int k = 0; k < VPT; ++k) {
                const int e = tid + k * 256;
                float4 v = make_float4(0.f, 0.f, 0.f, 0.f);
                if (e < valid_e) v = __ldcs(&src[e]);
                __stcs(&outp[e], v);
            }
        }
    }
}

extern "C" void kernel_launch(void* const* d_in, const int* in_sizes, int n_in,
                              void* d_out, int out_size) {
    const int F  = 512;
    const int F4 = F / 4;                                    // 128
    const int B  = in_sizes[1];
    const long long T = (long long)in_sizes[0] / F;
    const int max_sl = (int)((long long)out_size / ((long long)B * F));
    const int total  = out_size / 4;                         // float4 count

    if (F4 == 128 && max_sl == 4096 && B <= 32 && (total % 1024) == 0 &&
        T <= 0x7FFFFFFFLL) {
        fused_pad_scatter<7, 12, 4><<<total / 1024, 256>>>(
            (const float4*)d_in[0], (float4*)d_out, d_in[1], B);
    } else {
        build_offsets_kernel<<<1, 32>>>(d_in[1], B, T);
        pad_scatter_generic<<<(total + 255) / 256, 256>>>(
            (const float4*)d_in[0], (float4*)d_out, total, F4, max_sl);
    }
}

// round 12
// speedup vs baseline: 1.0418x; 1.0136x over previous
#include <cuda_runtime.h>
#include <cstdint>

// ---------------------------------------------------------------------------
// BatchedSequences: scatter concatenated rows S[T,F] into padded out[B,MAX,F],
// zero-filling padding. HBM-roofline copy.
// FINAL (best measured: 66.2us kernel, 6269 GB/s, 79.1% DRAM; run-to-run
// noise band +/-1.5-2us established by identical-code replays):
//   - single fused kernel, no prologue: per-block warp scan of lengths with
//     int32/int64 auto-detection (ballot probe on odd words)
//   - one block per 1024 contiguous float4 (8 rows); batch index is
//     block-uniform, so chunks specialize 3 ways: full-copy / all-padding /
//     boundary (<=1 per batch)
//   - 128-bit .cs streaming accesses; loads carry an L2::256B prefetch-
//     granule hint (sequential reads -> longer DRAM bursts). Measured A/Bs:
//     v8.f32 neutral alone, regressive stacked with the hint; write-back
//     stores regressive; persistent grid regressive; MLP 4 vs 8 neutral.
// ---------------------------------------------------------------------------

#define MAX_B 4096
__device__ int       g_len[MAX_B];
__device__ long long g_off[MAX_B];

// streaming load with 256B L2 prefetch granule
__device__ __forceinline__ float4 ldcs256(const float4* p) {
    float4 v;
    asm volatile("ld.global.cs.L2::256B.v4.f32 {%0,%1,%2,%3}, [%4];"
                 : "=f"(v.x), "=f"(v.y), "=f"(v.z), "=f"(v.w)
                 : "l"(p));
    return v;
}

// ---- generic fallback path (any B / shapes) --------------------------------
__global__ void build_offsets_kernel(const void* __restrict__ lens_raw,
                                     int B, long long T) {
    if (threadIdx.x == 0) {
        const int* v32 = (const int*)lens_raw;
        long long s = 0;
        for (int i = 0; i < B; ++i) s += (long long)v32[i];
        const bool is32 = (s == T);
        const long long* v64 = (const long long*)lens_raw;
        long long off = 0;
        for (int i = 0; i < B; ++i) {
            long long L = is32 ? (long long)v32[i] : v64[i];
            g_len[i] = (int)L;
            g_off[i] = off;
            off += L;
        }
    }
}

__global__ void __launch_bounds__(256)
pad_scatter_generic(const float4* __restrict__ in4,
                    float4* __restrict__ out4,
                    int total, int F4, int max_sl) {
    int idx = blockIdx.x * blockDim.x + threadIdx.x;
    if (idx >= total) return;
    int c   = idx % F4;
    int row = idx / F4;
    int b   = row / max_sl;
    int p   = row - b * max_sl;
    float4 v = make_float4(0.f, 0.f, 0.f, 0.f);
    if (p < g_len[b])
        v = __ldcs(&in4[(g_off[b] + (long long)p) * F4 + c]);
    __stcs(&out4[idx], v);
}

// ---- fused fast path (B <= 32, F4/MAX powers of two) ------------------------
// One block per CHUNK=1024 contiguous float4 (= 8 rows of F4=128). CHUNK
// divides MAX*F4, so the batch index is block-uniform and the len boundary
// cuts at most one chunk per batch. Source within a chunk is contiguous:
// src[e] = in4[(off+p0)*F4 + e].
template <int F4_LOG2, int MAX_LOG2, int VPT>
__global__ void __launch_bounds__(256)
fused_pad_scatter(const float4* __restrict__ in4,
                  float4* __restrict__ out4,
                  const void* __restrict__ lens_raw,
                  int B) {
    constexpr unsigned FULL  = 0xFFFFFFFFu;
    constexpr int CHUNK = 256 * VPT;
    constexpr int ROWS  = CHUNK >> F4_LOG2;          // rows per chunk

    const int tid  = threadIdx.x;
    const int lane = tid & 31;
    const int base = (int)blockIdx.x * CHUNK;
    const int b    = base >> (F4_LOG2 + MAX_LOG2);   // block-uniform

    // dtype probe: read first B int32 words (in-bounds for both layouts).
    // int32 lengths are positive -> some odd word nonzero; int64 (LE,
    // values < 2^31) -> odd words are all-zero high halves.
    const int* v32 = (const int*)lens_raw;
    int w = (lane < B) ? __ldg(&v32[lane]) : 0;
    const bool is32 = __ballot_sync(FULL, (lane & 1) && (w != 0)) != 0;
    int val = w;
    if (!is32) {                                     // warp-uniform branch
        const long long* v64 = (const long long*)lens_raw;
        val = (lane < B) ? (int)__ldg(&v64[lane]) : 0;
    }
    int incl = val;                                  // inclusive warp scan
    #pragma unroll
    for (int d = 1; d < 32; d <<= 1) {
        int y = __shfl_up_sync(FULL, incl, d);
        if (lane >= d) incl += y;
    }
    const int len = __shfl_sync(FULL, val,        b);
    const int off = __shfl_sync(FULL, incl - val, b);

    const int p0 = (base >> F4_LOG2) & ((1 << MAX_LOG2) - 1);  // first row
    float4* __restrict__ outp = out4 + base;

    if (p0 >= len) {
        // all-padding chunk: streaming zero stores only
        const float4 z = make_float4(0.f, 0.f, 0.f, 0.f);
        #pragma unroll
        for (int k = 0; k < VPT; ++k)
            __stcs(&outp[tid + k * 256], z);
    } else {
        const float4* __restrict__ src = in4 + ((off + p0) << F4_LOG2);
        if (p0 + ROWS <= len) {
            // fully valid chunk: streaming copy with 256B L2 read granules
            float4 v[VPT];
            #pragma unroll
            for (int k = 0; k < VPT; ++k)
                v[k] = ldcs256(&src[tid + k * 256]);
            #pragma unroll
            for (int k = 0; k < VPT; ++k)
                __stcs(&outp[tid + k * 256], v[k]);
        } else {
            // boundary chunk (<= 1 per batch): predicated
            const int valid_e = (len - p0) << F4_LOG2;
            #pragma unroll
            for (int k = 0; k < VPT; ++k) {
                const int e = tid + k * 256;
                float4 v = make_float4(0.f, 0.f, 0.f, 0.f);
                if (e < valid_e) v = __ldcs(&src[e]);
                __stcs(&outp[e], v);
            }
        }
    }
}

extern "C" void kernel_launch(void* const* d_in, const int* in_sizes, int n_in,
                              void* d_out, int out_size) {
    const int F  = 512;
    const int F4 = F / 4;                                    // 128
    const int B  = in_sizes[1];
    const long long T = (long long)in_sizes[0] / F;
    const int max_sl = (int)((long long)out_size / ((long long)B * F));
    const int total  = out_size / 4;                         // float4 count

    if (F4 == 128 && max_sl == 4096 && B <= 32 && (total % 1024) == 0 &&
        T <= 0x7FFFFFFFLL) {
        fused_pad_scatter<7, 12, 4><<<total / 1024, 256>>>(
            (const float4*)d_in[0], (float4*)d_out, d_in[1], B);
    } else {
        build_offsets_kernel<<<1, 32>>>(d_in[1], B, T);
        pad_scatter_generic<<<(total + 255) / 256, 256>>>(
            (const float4*)d_in[0], (float4*)d_out, total, F4, max_sl);
    }
}